// round 8
// baseline (speedup 1.0000x reference)
#include <cuda_runtime.h>
#include <cuda_fp16.h>
#include <math.h>
#include <stdint.h>

#define NROWS 8192
#define DIM 512
#define LOGIT_SCALE 2.659f
#define QSCALE 16.0f          // feature pre-scale before e4m3 quantization
#define INV_QS2 (1.0f / (QSCALE * QSCALE))

// ---------------- device scratch ----------------
__device__ uint8_t g_A8[NROWS * DIM];   // normalized image features (e4m3, x16)
__device__ uint8_t g_B8[NROWS * DIM];   // normalized text features (e4m3, x16)
__device__ float g_rowZ[NROWS], g_rowS[NROWS], g_colZ[NROWS], g_colS[NROWS];
__device__ int   g_lab[NROWS];
__device__ int   g_hist[1024];
__device__ int   g_is64;

// ---------------- fast exp on the FMA pipe (|x| <= ~3, rel err ~2e-6) ----------------
__device__ __forceinline__ float fexp(float s) {
    float t = s * 1.4426950408889634f;
    float z = t + 12582912.0f;
    int   n = __float_as_int(z) - 0x4B400000;
    float nf = z - 12582912.0f;
    float f = t - nf;
    float p = 1.3333558146e-3f;
    p = fmaf(p, f, 9.6181291076e-3f);
    p = fmaf(p, f, 5.5504108665e-2f);
    p = fmaf(p, f, 2.4022650696e-1f);
    p = fmaf(p, f, 6.9314718056e-1f);
    p = fmaf(p, f, 1.0f);
    return __int_as_float(__float_as_int(p) + (n << 23));
}

// ---------------- async copy helpers ----------------
#define CP_ASYNC16(dst, src) \
    asm volatile("cp.async.cg.shared.global [%0], [%1], 16;" :: "r"(dst), "l"(src))
#define CP_COMMIT() asm volatile("cp.async.commit_group;" ::: "memory")
#define CP_WAIT(n)  asm volatile("cp.async.wait_group %0;" :: "n"(n) : "memory")

__device__ __forceinline__ uint32_t smem_u32(const void* p) {
    uint32_t a;
    asm("{ .reg .u64 t; cvta.to.shared.u64 t, %1; cvt.u32.u64 %0, t; }" : "=r"(a) : "l"(p));
    return a;
}

__device__ __forceinline__ void ldmatrix_x4(uint32_t& r0, uint32_t& r1, uint32_t& r2,
                                            uint32_t& r3, uint32_t addr) {
    asm volatile("ldmatrix.sync.aligned.m8n8.x4.shared.b16 {%0,%1,%2,%3}, [%4];"
                 : "=r"(r0), "=r"(r1), "=r"(r2), "=r"(r3) : "r"(addr));
}

// e4m3 x e4m3 -> f16 accumulate, m16n8k32 (acc: 2 regs of half2)
__device__ __forceinline__ void mma_fp8_f16(uint32_t* d, const uint32_t* a,
                                            uint32_t b0, uint32_t b1) {
    asm volatile(
        "mma.sync.aligned.m16n8k32.row.col.f16.e4m3.e4m3.f16 "
        "{%0,%1}, {%2,%3,%4,%5}, {%6,%7}, {%0,%1};"
        : "+r"(d[0]), "+r"(d[1])
        : "r"(a[0]), "r"(a[1]), "r"(a[2]), "r"(a[3]), "r"(b0), "r"(b1));
}

// pack two floats into two e4m3 bytes (hi, lo)
__device__ __forceinline__ uint16_t pack_e4m3x2(float hi, float lo) {
    uint16_t r;
    asm("cvt.rn.satfinite.e4m3x2.f32 %0, %1, %2;" : "=h"(r) : "f"(hi), "f"(lo));
    return r;
}

// ---------------- launch 0: label dtype detect + zero hist ----------------
__global__ void k_detect(const int* __restrict__ w) {
    for (int i = threadIdx.x; i < 1024; i += blockDim.x) g_hist[i] = 0;
    int ok = 1;
    for (int p = threadIdx.x; p < 4096; p += blockDim.x) {
        int lo = w[2 * p], hi = w[2 * p + 1];
        if (hi != (lo >> 31)) ok = 0;
    }
    ok = __syncthreads_and(ok);
    if (threadIdx.x == 0) g_is64 = ok;
}

// ---------------- launch 1: decode labels + histogram + zero accumulators ----------------
__global__ void k_init(const void* __restrict__ labels) {
    int i = blockIdx.x * 256 + threadIdx.x;
    if (i >= NROWS) return;
    int lab = g_is64 ? (int)((const long long*)labels)[i] : ((const int*)labels)[i];
    g_lab[i] = lab;
    if (lab >= 0) atomicAdd(&g_hist[lab & 1023], 1);
    g_rowZ[i] = 0.f; g_rowS[i] = 0.f;
    g_colZ[i] = 0.f; g_colS[i] = 0.f;
}

// ---------------- launch 2: normalize + scale + cast to e4m3 ----------------
__global__ void k_norm(const float* __restrict__ img, const float* __restrict__ txt) {
    int b = blockIdx.x;
    const float* src; uint8_t* dst; int row;
    if (b < NROWS) { src = img; dst = g_A8; row = b; }
    else           { src = txt; dst = g_B8; row = b - NROWS; }
    float4 v = ((const float4*)(src + (size_t)row * DIM))[threadIdx.x];
    float ss = v.x * v.x + v.y * v.y + v.z * v.z + v.w * v.w;
#pragma unroll
    for (int m = 16; m; m >>= 1) ss += __shfl_xor_sync(0xffffffffu, ss, m);
    __shared__ float ws[4];
    if ((threadIdx.x & 31) == 0) ws[threadIdx.x >> 5] = ss;
    __syncthreads();
    float inv = QSCALE * rsqrtf(fmaxf(ws[0] + ws[1] + ws[2] + ws[3], 1e-24f));
    uint16_t lo = pack_e4m3x2(v.y * inv, v.x * inv);
    uint16_t hi = pack_e4m3x2(v.w * inv, v.z * inv);
    uint32_t o = (uint32_t)lo | ((uint32_t)hi << 16);
    *(uint32_t*)(dst + (size_t)row * DIM + threadIdx.x * 4) = o;
}

// ---------------- launch 3: fused fp8 GEMM (f16 acc) + softmax-stat epilogue ----------------
// CTA tile 128(m) x 128(n), BK=64 bytes, 2-stage cp.async double buffer,
// 4 warps in 2(m) x 2(n) grid -> warp tile 64x64, fp16 accumulators.
// __launch_bounds__(128, 5): 5 CTAs/SM = 20 warps, 102-reg budget.
// Smem stage: A 128x64B (8KB) + B 128x64B (8KB), 8-row x 16B blocked tiles:
//   tile t = (row>>3)*4 + (kbyte>>4), elem (row&7)*16  (ldmatrix.x4-friendly).
#define STAGE_BYTES 16384

__global__ __launch_bounds__(128, 5) void k_gemm() {
    extern __shared__ char smem[];
    const uint32_t sbase = smem_u32(smem);
    const int tid = threadIdx.x;
    const int lane = tid & 31, wid = tid >> 5;
    const int wm = wid & 1, wn = wid >> 1;            // 2 x 2 warp grid
    const int i0 = blockIdx.y * 128, j0 = blockIdx.x * 128;

    const int ldr = tid >> 2;        // 0..31 (row base; +32 per pass)
    const int ldc = tid & 3;         // 16-byte chunk within the 64B stage row

    const int g = lane >> 3;         // lane group 0..3
    const int lr = lane & 7;
    // affine ldmatrix bases: offset = base + mt*1024 + ks*256 (A), np*1024 + ks*256 (B)
    const uint32_t baseA = (uint32_t)(wm * 4096 + (g & 1) * 512 + (g >> 1) * 128 + lr * 16);
    const uint32_t baseB = (uint32_t)(8192 + wn * 4096 + (g >> 1) * 512 + (g & 1) * 128 + lr * 16);

    uint32_t acc[4][8][2];   // f16 accumulators (half2 pairs)
#pragma unroll
    for (int mt = 0; mt < 4; mt++)
#pragma unroll
        for (int nt = 0; nt < 8; nt++) { acc[mt][nt][0] = 0u; acc[mt][nt][1] = 0u; }

    auto load_stage = [&](int s, int kk) {
        uint32_t sA = sbase + s * STAGE_BYTES;
        uint32_t sB = sA + 8192;
#pragma unroll
        for (int h = 0; h < 4; h++) {
            int r = ldr + h * 32;
            uint32_t doff = (uint32_t)(((r >> 3) * 4 + ldc) * 128 + (r & 7) * 16);
            CP_ASYNC16(sA + doff, g_A8 + (size_t)(i0 + r) * DIM + kk + ldc * 16);
            CP_ASYNC16(sB + doff, g_B8 + (size_t)(j0 + r) * DIM + kk + ldc * 16);
        }
    };

    load_stage(0, 0);
    CP_COMMIT();

    for (int it = 0; it < 8; it++) {
        int s = it & 1;
        if (it + 1 < 8) {
            load_stage(s ^ 1, (it + 1) * 64);
            CP_COMMIT();
            CP_WAIT(1);
        } else {
            CP_WAIT(0);
        }
        __syncthreads();
        uint32_t stg = sbase + s * STAGE_BYTES;
#pragma unroll
        for (int ks = 0; ks < 2; ks++) {
            uint32_t A[4][4];
#pragma unroll
            for (int mt = 0; mt < 4; mt++)
                ldmatrix_x4(A[mt][0], A[mt][1], A[mt][2], A[mt][3],
                            stg + baseA + mt * 1024 + ks * 256);
#pragma unroll
            for (int np = 0; np < 4; np++) {
                uint32_t b0, b1, b2, b3;
                ldmatrix_x4(b0, b1, b2, b3, stg + baseB + np * 1024 + ks * 256);
#pragma unroll
                for (int mt = 0; mt < 4; mt++) {
                    mma_fp8_f16(acc[mt][np * 2],     A[mt], b0, b1);
                    mma_fp8_f16(acc[mt][np * 2 + 1], A[mt], b2, b3);
                }
            }
        }
        __syncthreads();
    }

    // ---- epilogue: logits -> exp + target-weighted stats (registers only) ----
    // acc[mt][nt][hb] is half2 {col c, col c+1} for row (lane>>2)+mt*16+hb*8,
    // cols c = 2*(lane&3)+nt*8.  Values carry x256 (QSCALE^2) scale.
    const int r_base = i0 + wm * 64 + (lane >> 2);
    const int c_base = j0 + wn * 64 + 2 * (lane & 3);
    const float lsc = LOGIT_SCALE * INV_QS2;

    int labR[8];
#pragma unroll
    for (int q = 0; q < 8; q++) labR[q] = g_lab[r_base + (q >> 1) * 16 + (q & 1) * 8];
    int labC[16];
#pragma unroll
    for (int nt = 0; nt < 8; nt++) {
        labC[nt * 2]     = g_lab[c_base + nt * 8];
        labC[nt * 2 + 1] = g_lab[c_base + nt * 8 + 1];
    }

    float rZ[8], rS[8], cZ[16], cS[16];
#pragma unroll
    for (int q = 0; q < 8; q++) { rZ[q] = 0.f; rS[q] = 0.f; }
#pragma unroll
    for (int q = 0; q < 16; q++) { cZ[q] = 0.f; cS[q] = 0.f; }

#pragma unroll
    for (int mt = 0; mt < 4; mt++)
#pragma unroll
        for (int nt = 0; nt < 8; nt++)
#pragma unroll
            for (int hb = 0; hb < 2; hb++) {
                float2 pv = __half22float2(*(__half2*)&acc[mt][nt][hb]);
                int gi = r_base + mt * 16 + hb * 8;
                int li = labR[mt * 2 + hb];
#pragma unroll
                for (int d = 0; d < 2; d++) {
                    float sv = lsc * (d ? pv.y : pv.x);
                    float ex = fexp(sv);
                    int gj = c_base + nt * 8 + d;
                    bool tg = (gi == gj) || (li >= 0 && li == labC[nt * 2 + d]);
                    float ms = tg ? sv : 0.f;
                    rZ[mt * 2 + hb] += ex; rS[mt * 2 + hb] += ms;
                    cZ[nt * 2 + d] += ex;  cS[nt * 2 + d] += ms;
                }
            }

    // rows: reduce across the 4 lanes of each quad
#pragma unroll
    for (int m = 1; m <= 2; m <<= 1)
#pragma unroll
        for (int q = 0; q < 8; q++) {
            rZ[q] += __shfl_xor_sync(0xffffffffu, rZ[q], m);
            rS[q] += __shfl_xor_sync(0xffffffffu, rS[q], m);
        }
    if ((lane & 3) == 0) {
#pragma unroll
        for (int q = 0; q < 8; q++) {
            int gi = r_base + (q >> 1) * 16 + (q & 1) * 8;
            atomicAdd(&g_rowZ[gi], rZ[q]);
            atomicAdd(&g_rowS[gi], rS[q]);
        }
    }

    // cols: reduce across lane>>2
#pragma unroll
    for (int m = 4; m <= 16; m <<= 1)
#pragma unroll
        for (int q = 0; q < 16; q++) {
            cZ[q] += __shfl_xor_sync(0xffffffffu, cZ[q], m);
            cS[q] += __shfl_xor_sync(0xffffffffu, cS[q], m);
        }
    if (lane < 4) {
#pragma unroll
        for (int q = 0; q < 16; q++) {
            int gj = j0 + wn * 64 + (q >> 1) * 8 + 2 * lane + (q & 1);
            atomicAdd(&g_colZ[gj], cZ[q]);
            atomicAdd(&g_colS[gj], cS[q]);
        }
    }
}

// ---------------- launch 4: final reduction ----------------
__global__ void k_final(float* __restrict__ out) {
    int tid = threadIdx.x;
    float sum = 0.f;
    for (int i = tid; i < NROWS; i += 1024) {
        int l = g_lab[i];
        float inv = (l < 0) ? 1.f : 1.f / (float)g_hist[l & 1023];
        sum += logf(g_rowZ[i]) + logf(g_colZ[i]) - (g_rowS[i] + g_colS[i]) * inv;
    }
#pragma unroll
    for (int m = 16; m; m >>= 1) sum += __shfl_xor_sync(0xffffffffu, sum, m);
    __shared__ float ws[32];
    if ((tid & 31) == 0) ws[tid >> 5] = sum;
    __syncthreads();
    if (tid < 32) {
        float v = ws[tid];
#pragma unroll
        for (int m = 16; m; m >>= 1) v += __shfl_xor_sync(0xffffffffu, v, m);
        if (tid == 0) out[0] = v / (2.0f * NROWS);
    }
}

// ---------------- launch ----------------
extern "C" void kernel_launch(void* const* d_in, const int* in_sizes, int n_in,
                              void* d_out, int out_size) {
    const float* txt = (const float*)d_in[0];
    const float* img = (const float*)d_in[1];
    const void*  lab = d_in[2];

    cudaFuncSetAttribute(k_gemm, cudaFuncAttributeMaxDynamicSharedMemorySize,
                         2 * STAGE_BYTES);

    k_detect<<<1, 256>>>((const int*)lab);            // launch 0
    k_init<<<32, 256>>>(lab);                         // launch 1 (labels+hist+zero)
    k_norm<<<2 * NROWS, 128>>>(img, txt);             // launch 2
    dim3 grid(64, 64);
    k_gemm<<<grid, 128, 2 * STAGE_BYTES>>>();         // launch 3  <- ncu -s captures here
    k_final<<<1, 1024>>>((float*)d_out);              // launch 4
}

// round 9
// speedup vs baseline: 1.0294x; 1.0294x over previous
#include <cuda_runtime.h>
#include <cuda_fp16.h>
#include <math.h>
#include <stdint.h>

#define NROWS 8192
#define DIM 512
#define LOGIT_SCALE 2.659f
#define QSCALE 16.0f          // feature pre-scale before e4m3 quantization
#define INV_QS2 (1.0f / (QSCALE * QSCALE))

// ---------------- device scratch ----------------
__device__ uint8_t g_A8[NROWS * DIM];   // normalized image features (e4m3, x16)
__device__ uint8_t g_B8[NROWS * DIM];   // normalized text features (e4m3, x16)
__device__ float g_rowZ[NROWS], g_rowS[NROWS], g_colZ[NROWS], g_colS[NROWS];
__device__ int   g_lab[NROWS];
__device__ int   g_hist[1024];
__device__ int   g_is64;

// ---------------- fast exp on the FMA pipe (|x| <= ~3, rel err ~2e-6) ----------------
__device__ __forceinline__ float fexp(float s) {
    float t = s * 1.4426950408889634f;
    float z = t + 12582912.0f;
    int   n = __float_as_int(z) - 0x4B400000;
    float nf = z - 12582912.0f;
    float f = t - nf;
    float p = 1.3333558146e-3f;
    p = fmaf(p, f, 9.6181291076e-3f);
    p = fmaf(p, f, 5.5504108665e-2f);
    p = fmaf(p, f, 2.4022650696e-1f);
    p = fmaf(p, f, 6.9314718056e-1f);
    p = fmaf(p, f, 1.0f);
    return __int_as_float(__float_as_int(p) + (n << 23));
}

// ---------------- async copy helpers ----------------
#define CP_ASYNC16(dst, src) \
    asm volatile("cp.async.cg.shared.global [%0], [%1], 16;" :: "r"(dst), "l"(src))
#define CP_COMMIT() asm volatile("cp.async.commit_group;" ::: "memory")
#define CP_WAIT(n)  asm volatile("cp.async.wait_group %0;" :: "n"(n) : "memory")

__device__ __forceinline__ uint32_t smem_u32(const void* p) {
    uint32_t a;
    asm("{ .reg .u64 t; cvta.to.shared.u64 t, %1; cvt.u32.u64 %0, t; }" : "=r"(a) : "l"(p));
    return a;
}

__device__ __forceinline__ void ldmatrix_x4(uint32_t& r0, uint32_t& r1, uint32_t& r2,
                                            uint32_t& r3, uint32_t addr) {
    asm volatile("ldmatrix.sync.aligned.m8n8.x4.shared.b16 {%0,%1,%2,%3}, [%4];"
                 : "=r"(r0), "=r"(r1), "=r"(r2), "=r"(r3) : "r"(addr));
}

// e4m3 x e4m3 -> f16 accumulate, m16n8k32 (acc: 2 regs of half2)
__device__ __forceinline__ void mma_fp8_f16(uint32_t* d, const uint32_t* a,
                                            uint32_t b0, uint32_t b1) {
    asm volatile(
        "mma.sync.aligned.m16n8k32.row.col.f16.e4m3.e4m3.f16 "
        "{%0,%1}, {%2,%3,%4,%5}, {%6,%7}, {%0,%1};"
        : "+r"(d[0]), "+r"(d[1])
        : "r"(a[0]), "r"(a[1]), "r"(a[2]), "r"(a[3]), "r"(b0), "r"(b1));
}

// pack two floats into two e4m3 bytes (hi, lo)
__device__ __forceinline__ uint16_t pack_e4m3x2(float hi, float lo) {
    uint16_t r;
    asm("cvt.rn.satfinite.e4m3x2.f32 %0, %1, %2;" : "=h"(r) : "f"(hi), "f"(lo));
    return r;
}

// ---------------- launch 0: label dtype detect + zero hist ----------------
__global__ void k_detect(const int* __restrict__ w) {
    for (int i = threadIdx.x; i < 1024; i += blockDim.x) g_hist[i] = 0;
    int ok = 1;
    for (int p = threadIdx.x; p < 4096; p += blockDim.x) {
        int lo = w[2 * p], hi = w[2 * p + 1];
        if (hi != (lo >> 31)) ok = 0;
    }
    ok = __syncthreads_and(ok);
    if (threadIdx.x == 0) g_is64 = ok;
}

// ---------------- launch 1: decode labels + histogram + zero accumulators ----------------
__global__ void k_init(const void* __restrict__ labels) {
    int i = blockIdx.x * 256 + threadIdx.x;
    if (i >= NROWS) return;
    int lab = g_is64 ? (int)((const long long*)labels)[i] : ((const int*)labels)[i];
    g_lab[i] = lab;
    if (lab >= 0) atomicAdd(&g_hist[lab & 1023], 1);
    g_rowZ[i] = 0.f; g_rowS[i] = 0.f;
    g_colZ[i] = 0.f; g_colS[i] = 0.f;
}

// ---------------- launch 2: normalize + scale + cast to e4m3 ----------------
__global__ void k_norm(const float* __restrict__ img, const float* __restrict__ txt) {
    int b = blockIdx.x;
    const float* src; uint8_t* dst; int row;
    if (b < NROWS) { src = img; dst = g_A8; row = b; }
    else           { src = txt; dst = g_B8; row = b - NROWS; }
    float4 v = ((const float4*)(src + (size_t)row * DIM))[threadIdx.x];
    float ss = v.x * v.x + v.y * v.y + v.z * v.z + v.w * v.w;
#pragma unroll
    for (int m = 16; m; m >>= 1) ss += __shfl_xor_sync(0xffffffffu, ss, m);
    __shared__ float ws[4];
    if ((threadIdx.x & 31) == 0) ws[threadIdx.x >> 5] = ss;
    __syncthreads();
    float inv = QSCALE * rsqrtf(fmaxf(ws[0] + ws[1] + ws[2] + ws[3], 1e-24f));
    uint16_t lo = pack_e4m3x2(v.y * inv, v.x * inv);
    uint16_t hi = pack_e4m3x2(v.w * inv, v.z * inv);
    uint32_t o = (uint32_t)lo | ((uint32_t)hi << 16);
    *(uint32_t*)(dst + (size_t)row * DIM + threadIdx.x * 4) = o;
}

// ---------------- launch 3: fused fp8 GEMM (f16 acc) + softmax-stat epilogue ----------------
// CTA tile 128(m) x 256(n), BK=64 bytes, 3-stage cp.async pipeline.
// 16 warps in 2(m) x 8(n) grid -> warp tile 64x32, fp16 acc = 32 regs.
// __launch_bounds__(512, 2): 2 CTAs/SM = 32 warps, 64-reg budget.
// Smem stage: A 128x64B (8KB) + B 256x64B (16KB), 8-row x 16B blocked tiles:
//   tile t = (row>>3)*4 + (kbyte>>4), elem (row&7)*16  (ldmatrix.x4-friendly).
#define STAGE_BYTES 24576

__global__ __launch_bounds__(512, 2) void k_gemm() {
    extern __shared__ char smem[];
    const uint32_t sbase = smem_u32(smem);
    const int tid = threadIdx.x;
    const int lane = tid & 31, wid = tid >> 5;
    const int wm = wid & 1, wn = wid >> 1;            // 2 x 8 warp grid
    const int i0 = blockIdx.y * 128, j0 = blockIdx.x * 256;

    const int g = lane >> 3;         // lane group 0..3
    const int lr = lane & 7;
    // affine ldmatrix bases (stage-relative):
    //   A addr = stg + aBase + mt*1024 + ks*256      (16 rows x 32 kbytes per x4)
    //   B addr = stg + bBase + np*1024 + ks*256      (16 j-rows x 32 kbytes per x4)
    const uint32_t aBase = (uint32_t)((wm * 8 + (g & 1)) * 512 + (g >> 1) * 128 + lr * 16);
    const uint32_t bBase = (uint32_t)(8192 + (wn * 4 + (g >> 1)) * 512 + (g & 1) * 128 + lr * 16);

    // loader: 512 threads; A 512 vecs (1/thread), B 1024 vecs (2/thread)
    const int ldr = tid >> 2;        // 0..127
    const int ldc = tid & 3;         // 16-byte chunk within the 64B stage row
    const uint32_t dA = (uint32_t)(((ldr >> 3) * 4 + ldc) * 128 + (ldr & 7) * 16);
    const uint8_t* pA = g_A8 + (size_t)(i0 + ldr) * DIM + ldc * 16;
    const uint8_t* pB = g_B8 + (size_t)(j0 + ldr) * DIM + ldc * 16;

    uint32_t acc[4][4][2];   // f16 accumulators (half2 pairs), warp tile 64x32
#pragma unroll
    for (int mt = 0; mt < 4; mt++)
#pragma unroll
        for (int nt = 0; nt < 4; nt++) { acc[mt][nt][0] = 0u; acc[mt][nt][1] = 0u; }

    auto load_stage = [&](int s, int kk) {
        uint32_t sA = sbase + s * STAGE_BYTES;
        CP_ASYNC16(sA + dA, pA + kk);
        CP_ASYNC16(sA + 8192 + dA, pB + kk);                       // B rows 0..127
        CP_ASYNC16(sA + 8192 + dA + 8192, pB + kk + 128 * DIM);    // B rows 128..255
    };

    load_stage(0, 0);
    CP_COMMIT();
    load_stage(1, 64);
    CP_COMMIT();

    int slot = 0, nslot = 2;
    for (int it = 0; it < 8; it++) {
        if (it <= 5) CP_WAIT(1); else CP_WAIT(0);
        __syncthreads();
        if (it + 2 <= 7) {
            load_stage(nslot, (it + 2) * 64);
            CP_COMMIT();
        }
        uint32_t stg = sbase + slot * STAGE_BYTES;
#pragma unroll
        for (int ks = 0; ks < 2; ks++) {
            uint32_t A[4][4];
#pragma unroll
            for (int mt = 0; mt < 4; mt++)
                ldmatrix_x4(A[mt][0], A[mt][1], A[mt][2], A[mt][3],
                            stg + aBase + mt * 1024 + ks * 256);
#pragma unroll
            for (int np = 0; np < 2; np++) {
                uint32_t b0, b1, b2, b3;
                ldmatrix_x4(b0, b1, b2, b3, stg + bBase + np * 1024 + ks * 256);
#pragma unroll
                for (int mt = 0; mt < 4; mt++) {
                    mma_fp8_f16(acc[mt][np * 2],     A[mt], b0, b1);
                    mma_fp8_f16(acc[mt][np * 2 + 1], A[mt], b2, b3);
                }
            }
        }
        slot = (slot == 2) ? 0 : slot + 1;
        nslot = (nslot == 2) ? 0 : nslot + 1;
    }

    // ---- epilogue: logits -> exp + target-weighted stats (registers only) ----
    // acc[mt][nt][hb] = half2 {col c, col c+1}, row (lane>>2)+mt*16+hb*8,
    // cols c = 2*(lane&3)+nt*8.  Values carry x256 (QSCALE^2) scale.
    const int r_base = i0 + wm * 64 + (lane >> 2);
    const int c_base = j0 + wn * 32 + 2 * (lane & 3);
    const float lsc = LOGIT_SCALE * INV_QS2;

    int labR[8];
#pragma unroll
    for (int q = 0; q < 8; q++) labR[q] = g_lab[r_base + (q >> 1) * 16 + (q & 1) * 8];
    int labC[8];
#pragma unroll
    for (int nt = 0; nt < 4; nt++) {
        labC[nt * 2]     = g_lab[c_base + nt * 8];
        labC[nt * 2 + 1] = g_lab[c_base + nt * 8 + 1];
    }

    float rZ[8], rS[8], cZ[8], cS[8];
#pragma unroll
    for (int q = 0; q < 8; q++) { rZ[q] = 0.f; rS[q] = 0.f; cZ[q] = 0.f; cS[q] = 0.f; }

#pragma unroll
    for (int mt = 0; mt < 4; mt++)
#pragma unroll
        for (int nt = 0; nt < 4; nt++)
#pragma unroll
            for (int hb = 0; hb < 2; hb++) {
                float2 pv = __half22float2(*(__half2*)&acc[mt][nt][hb]);
                int gi = r_base + mt * 16 + hb * 8;
                int li = labR[mt * 2 + hb];
#pragma unroll
                for (int d = 0; d < 2; d++) {
                    float sv = lsc * (d ? pv.y : pv.x);
                    float ex = fexp(sv);
                    int gj = c_base + nt * 8 + d;
                    bool tg = (gi == gj) || (li >= 0 && li == labC[nt * 2 + d]);
                    float ms = tg ? sv : 0.f;
                    rZ[mt * 2 + hb] += ex; rS[mt * 2 + hb] += ms;
                    cZ[nt * 2 + d] += ex;  cS[nt * 2 + d] += ms;
                }
            }

    // rows: reduce across the 4 lanes of each quad
#pragma unroll
    for (int m = 1; m <= 2; m <<= 1)
#pragma unroll
        for (int q = 0; q < 8; q++) {
            rZ[q] += __shfl_xor_sync(0xffffffffu, rZ[q], m);
            rS[q] += __shfl_xor_sync(0xffffffffu, rS[q], m);
        }
    if ((lane & 3) == 0) {
#pragma unroll
        for (int q = 0; q < 8; q++) {
            int gi = r_base + (q >> 1) * 16 + (q & 1) * 8;
            atomicAdd(&g_rowZ[gi], rZ[q]);
            atomicAdd(&g_rowS[gi], rS[q]);
        }
    }

    // cols: reduce across lane>>2
#pragma unroll
    for (int m = 4; m <= 16; m <<= 1)
#pragma unroll
        for (int q = 0; q < 8; q++) {
            cZ[q] += __shfl_xor_sync(0xffffffffu, cZ[q], m);
            cS[q] += __shfl_xor_sync(0xffffffffu, cS[q], m);
        }
    if (lane < 4) {
#pragma unroll
        for (int q = 0; q < 8; q++) {
            int gj = j0 + wn * 32 + (q >> 1) * 8 + 2 * lane + (q & 1);
            atomicAdd(&g_colZ[gj], cZ[q]);
            atomicAdd(&g_colS[gj], cS[q]);
        }
    }
}

// ---------------- launch 4: final reduction ----------------
__global__ void k_final(float* __restrict__ out) {
    int tid = threadIdx.x;
    float sum = 0.f;
    for (int i = tid; i < NROWS; i += 1024) {
        int l = g_lab[i];
        float inv = (l < 0) ? 1.f : 1.f / (float)g_hist[l & 1023];
        sum += logf(g_rowZ[i]) + logf(g_colZ[i]) - (g_rowS[i] + g_colS[i]) * inv;
    }
#pragma unroll
    for (int m = 16; m; m >>= 1) sum += __shfl_xor_sync(0xffffffffu, sum, m);
    __shared__ float ws[32];
    if ((tid & 31) == 0) ws[tid >> 5] = sum;
    __syncthreads();
    if (tid < 32) {
        float v = ws[tid];
#pragma unroll
        for (int m = 16; m; m >>= 1) v += __shfl_xor_sync(0xffffffffu, v, m);
        if (tid == 0) out[0] = v / (2.0f * NROWS);
    }
}

// ---------------- launch ----------------
extern "C" void kernel_launch(void* const* d_in, const int* in_sizes, int n_in,
                              void* d_out, int out_size) {
    const float* txt = (const float*)d_in[0];
    const float* img = (const float*)d_in[1];
    const void*  lab = d_in[2];

    cudaFuncSetAttribute(k_gemm, cudaFuncAttributeMaxDynamicSharedMemorySize,
                         3 * STAGE_BYTES);

    k_detect<<<1, 256>>>((const int*)lab);            // launch 0
    k_init<<<32, 256>>>(lab);                         // launch 1 (labels+hist+zero)
    k_norm<<<2 * NROWS, 128>>>(img, txt);             // launch 2
    dim3 grid(32, 64);
    k_gemm<<<grid, 512, 3 * STAGE_BYTES>>>();         // launch 3  <- ncu -s captures here
    k_final<<<1, 1024>>>((float*)d_out);              // launch 4
}

// round 10
// speedup vs baseline: 1.1158x; 1.0839x over previous
#include <cuda_runtime.h>
#include <cuda_fp16.h>
#include <math.h>
#include <stdint.h>

#define NROWS 8192
#define DIM 512
#define LOGIT_SCALE 2.659f
#define QSCALE 16.0f          // feature pre-scale before e4m3 quantization
#define INV_QS2 (1.0f / (QSCALE * QSCALE))

// ---------------- device scratch ----------------
__device__ uint8_t g_A8[NROWS * DIM];   // normalized image features (e4m3, x16)
__device__ uint8_t g_B8[NROWS * DIM];   // normalized text features (e4m3, x16)
__device__ float g_rowZ[NROWS], g_rowS[NROWS], g_colZ[NROWS], g_colS[NROWS];
__device__ int   g_lab[NROWS];
__device__ int   g_hist[1024];
__device__ int   g_is64;

// ---------------- fast exp on the FMA pipe (|x| <= ~3, rel err ~2e-6) ----------------
__device__ __forceinline__ float fexp(float s) {
    float t = s * 1.4426950408889634f;
    float z = t + 12582912.0f;
    int   n = __float_as_int(z) - 0x4B400000;
    float nf = z - 12582912.0f;
    float f = t - nf;
    float p = 1.3333558146e-3f;
    p = fmaf(p, f, 9.6181291076e-3f);
    p = fmaf(p, f, 5.5504108665e-2f);
    p = fmaf(p, f, 2.4022650696e-1f);
    p = fmaf(p, f, 6.9314718056e-1f);
    p = fmaf(p, f, 1.0f);
    return __int_as_float(__float_as_int(p) + (n << 23));
}

// ---------------- async copy helpers ----------------
#define CP_ASYNC16(dst, src) \
    asm volatile("cp.async.cg.shared.global [%0], [%1], 16;" :: "r"(dst), "l"(src))
#define CP_COMMIT() asm volatile("cp.async.commit_group;" ::: "memory")
#define CP_WAIT(n)  asm volatile("cp.async.wait_group %0;" :: "n"(n) : "memory")

__device__ __forceinline__ uint32_t smem_u32(const void* p) {
    uint32_t a;
    asm("{ .reg .u64 t; cvta.to.shared.u64 t, %1; cvt.u32.u64 %0, t; }" : "=r"(a) : "l"(p));
    return a;
}

__device__ __forceinline__ void ldmatrix_x4(uint32_t& r0, uint32_t& r1, uint32_t& r2,
                                            uint32_t& r3, uint32_t addr) {
    asm volatile("ldmatrix.sync.aligned.m8n8.x4.shared.b16 {%0,%1,%2,%3}, [%4];"
                 : "=r"(r0), "=r"(r1), "=r"(r2), "=r"(r3) : "r"(addr));
}

// e4m3 x e4m3 -> f16 accumulate, m16n8k32 (acc: 2 regs of half2)
__device__ __forceinline__ void mma_fp8_f16(uint32_t* d, const uint32_t* a,
                                            uint32_t b0, uint32_t b1) {
    asm volatile(
        "mma.sync.aligned.m16n8k32.row.col.f16.e4m3.e4m3.f16 "
        "{%0,%1}, {%2,%3,%4,%5}, {%6,%7}, {%0,%1};"
        : "+r"(d[0]), "+r"(d[1])
        : "r"(a[0]), "r"(a[1]), "r"(a[2]), "r"(a[3]), "r"(b0), "r"(b1));
}

// pack two floats into two e4m3 bytes (hi, lo)
__device__ __forceinline__ uint16_t pack_e4m3x2(float hi, float lo) {
    uint16_t r;
    asm("cvt.rn.satfinite.e4m3x2.f32 %0, %1, %2;" : "=h"(r) : "f"(hi), "f"(lo));
    return r;
}

// ---------------- launch 0: label dtype detect + zero hist ----------------
__global__ void k_detect(const int* __restrict__ w) {
    for (int i = threadIdx.x; i < 1024; i += blockDim.x) g_hist[i] = 0;
    int ok = 1;
    for (int p = threadIdx.x; p < 4096; p += blockDim.x) {
        int lo = w[2 * p], hi = w[2 * p + 1];
        if (hi != (lo >> 31)) ok = 0;
    }
    ok = __syncthreads_and(ok);
    if (threadIdx.x == 0) g_is64 = ok;
}

// ---------------- launch 1: decode labels + histogram + zero accumulators ----------------
__global__ void k_init(const void* __restrict__ labels) {
    int i = blockIdx.x * 256 + threadIdx.x;
    if (i >= NROWS) return;
    int lab = g_is64 ? (int)((const long long*)labels)[i] : ((const int*)labels)[i];
    g_lab[i] = lab;
    if (lab >= 0) atomicAdd(&g_hist[lab & 1023], 1);
    g_rowZ[i] = 0.f; g_rowS[i] = 0.f;
    g_colZ[i] = 0.f; g_colS[i] = 0.f;
}

// ---------------- launch 2: normalize + scale + cast to e4m3 ----------------
__global__ void k_norm(const float* __restrict__ img, const float* __restrict__ txt) {
    int b = blockIdx.x;
    const float* src; uint8_t* dst; int row;
    if (b < NROWS) { src = img; dst = g_A8; row = b; }
    else           { src = txt; dst = g_B8; row = b - NROWS; }
    float4 v = ((const float4*)(src + (size_t)row * DIM))[threadIdx.x];
    float ss = v.x * v.x + v.y * v.y + v.z * v.z + v.w * v.w;
#pragma unroll
    for (int m = 16; m; m >>= 1) ss += __shfl_xor_sync(0xffffffffu, ss, m);
    __shared__ float ws[4];
    if ((threadIdx.x & 31) == 0) ws[threadIdx.x >> 5] = ss;
    __syncthreads();
    float inv = QSCALE * rsqrtf(fmaxf(ws[0] + ws[1] + ws[2] + ws[3], 1e-24f));
    uint16_t lo = pack_e4m3x2(v.y * inv, v.x * inv);
    uint16_t hi = pack_e4m3x2(v.w * inv, v.z * inv);
    uint32_t o = (uint32_t)lo | ((uint32_t)hi << 16);
    *(uint32_t*)(dst + (size_t)row * DIM + threadIdx.x * 4) = o;
}

// ---------------- launch 3: fused fp8 GEMM (f16 acc) + softmax-stat epilogue ----------------
// CTA tile 128(m) x 256(n), BK=128 bytes (quarter of K), 2-stage double buffer,
// 4 mainloop iterations, ONE barrier per iteration (sync before load-issue —
// no cross-thread overwrite hazard). 8 warps in 2(m) x 4(n) grid -> warp tile
// 64x64, fp16 accumulators. 2 CTAs/SM (96KB smem each, 192KB total).
// Smem stage: A 128x128B (16KB) + B 256x128B (32KB), 8-row x 16B blocked tiles:
//   off(r,c) = ((r>>3)*8 + (c>>4))*128 + (r&7)*16      (ldmatrix.x4-friendly)
#define STAGE_BYTES 49152

__global__ __launch_bounds__(256, 2) void k_gemm() {
    extern __shared__ char smem[];
    const uint32_t sbase = smem_u32(smem);
    const int tid = threadIdx.x;
    const int lane = tid & 31, wid = tid >> 5;
    const int wm = wid & 1, wn = wid >> 1;            // 2 x 4 warp grid
    const int i0 = blockIdx.y * 128, j0 = blockIdx.x * 256;

    const int g = lane >> 3;         // lane group 0..3
    const int lr = lane & 7;
    // affine ldmatrix bases (stage-relative); +mt*2048 / +np*2048, +ks*256
    const uint32_t aBase = (uint32_t)(wm * 8192 + (g & 1) * 1024 + (g >> 1) * 128 + lr * 16);
    const uint32_t bBase = (uint32_t)(16384 + wn * 8192 + (g >> 1) * 1024 + (g & 1) * 128 + lr * 16);

    // loader: 256 threads; A 1024 vec16 (4/thread), B 2048 vec16 (8/thread)
    const int r0  = tid >> 3;        // 0..31
    const int seg = tid & 7;         // 16B chunk within the 128B stage row
    const uint32_t dBase = (uint32_t)(((r0 >> 3) * 8 + seg) * 128 + (r0 & 7) * 16);
    const uint8_t* pA = g_A8 + (size_t)(i0 + r0) * DIM + seg * 16;
    const uint8_t* pB = g_B8 + (size_t)(j0 + r0) * DIM + seg * 16;

    uint32_t acc[4][8][2];   // f16 accumulators (half2 pairs), warp tile 64x64
#pragma unroll
    for (int mt = 0; mt < 4; mt++)
#pragma unroll
        for (int nt = 0; nt < 8; nt++) { acc[mt][nt][0] = 0u; acc[mt][nt][1] = 0u; }

    auto load_stage = [&](int s, int kk) {
        uint32_t sA = sbase + s * STAGE_BYTES;
        uint32_t sB = sA + 16384;
#pragma unroll
        for (int t = 0; t < 4; t++)
            CP_ASYNC16(sA + dBase + t * 4096, pA + (size_t)(32 * t) * DIM + kk);
#pragma unroll
        for (int t = 0; t < 8; t++)
            CP_ASYNC16(sB + dBase + t * 4096, pB + (size_t)(32 * t) * DIM + kk);
    };

    load_stage(0, 0);
    CP_COMMIT();

    for (int it = 0; it < 4; it++) {
        CP_WAIT(0);
        __syncthreads();
        if (it + 1 < 4) {
            load_stage((it + 1) & 1, (it + 1) * 128);
            CP_COMMIT();
        }
        uint32_t stg = sbase + (it & 1) * STAGE_BYTES;
#pragma unroll
        for (int ks = 0; ks < 4; ks++) {
            uint32_t A[4][4];
#pragma unroll
            for (int mt = 0; mt < 4; mt++)
                ldmatrix_x4(A[mt][0], A[mt][1], A[mt][2], A[mt][3],
                            stg + aBase + mt * 2048 + ks * 256);
#pragma unroll
            for (int np = 0; np < 4; np++) {
                uint32_t b0, b1, b2, b3;
                ldmatrix_x4(b0, b1, b2, b3, stg + bBase + np * 2048 + ks * 256);
#pragma unroll
                for (int mt = 0; mt < 4; mt++) {
                    mma_fp8_f16(acc[mt][np * 2],     A[mt], b0, b1);
                    mma_fp8_f16(acc[mt][np * 2 + 1], A[mt], b2, b3);
                }
            }
        }
    }

    // ---- epilogue: logits -> exp + target-weighted stats (registers only) ----
    // acc[mt][nt][hb] = half2 {col c, col c+1}, row (lane>>2)+mt*16+hb*8,
    // cols c = 2*(lane&3)+nt*8.  Values carry x256 (QSCALE^2) scale.
    const int r_base = i0 + wm * 64 + (lane >> 2);
    const int c_base = j0 + wn * 64 + 2 * (lane & 3);
    const float lsc = LOGIT_SCALE * INV_QS2;

    int labR[8];
#pragma unroll
    for (int q = 0; q < 8; q++) labR[q] = g_lab[r_base + (q >> 1) * 16 + (q & 1) * 8];
    int labC[16];
#pragma unroll
    for (int nt = 0; nt < 8; nt++) {
        labC[nt * 2]     = g_lab[c_base + nt * 8];
        labC[nt * 2 + 1] = g_lab[c_base + nt * 8 + 1];
    }

    float rZ[8], rS[8], cZ[16], cS[16];
#pragma unroll
    for (int q = 0; q < 8; q++) { rZ[q] = 0.f; rS[q] = 0.f; }
#pragma unroll
    for (int q = 0; q < 16; q++) { cZ[q] = 0.f; cS[q] = 0.f; }

#pragma unroll
    for (int mt = 0; mt < 4; mt++)
#pragma unroll
        for (int nt = 0; nt < 8; nt++)
#pragma unroll
            for (int hb = 0; hb < 2; hb++) {
                float2 pv = __half22float2(*(__half2*)&acc[mt][nt][hb]);
                int gi = r_base + mt * 16 + hb * 8;
                int li = labR[mt * 2 + hb];
#pragma unroll
                for (int d = 0; d < 2; d++) {
                    float sv = lsc * (d ? pv.y : pv.x);
                    float ex = fexp(sv);
                    int gj = c_base + nt * 8 + d;
                    bool tg = (gi == gj) || (li >= 0 && li == labC[nt * 2 + d]);
                    float ms = tg ? sv : 0.f;
                    rZ[mt * 2 + hb] += ex; rS[mt * 2 + hb] += ms;
                    cZ[nt * 2 + d] += ex;  cS[nt * 2 + d] += ms;
                }
            }

    // rows: reduce across the 4 lanes of each quad
#pragma unroll
    for (int m = 1; m <= 2; m <<= 1)
#pragma unroll
        for (int q = 0; q < 8; q++) {
            rZ[q] += __shfl_xor_sync(0xffffffffu, rZ[q], m);
            rS[q] += __shfl_xor_sync(0xffffffffu, rS[q], m);
        }
    if ((lane & 3) == 0) {
#pragma unroll
        for (int q = 0; q < 8; q++) {
            int gi = r_base + (q >> 1) * 16 + (q & 1) * 8;
            atomicAdd(&g_rowZ[gi], rZ[q]);
            atomicAdd(&g_rowS[gi], rS[q]);
        }
    }

    // cols: reduce across lane>>2
#pragma unroll
    for (int m = 4; m <= 16; m <<= 1)
#pragma unroll
        for (int q = 0; q < 16; q++) {
            cZ[q] += __shfl_xor_sync(0xffffffffu, cZ[q], m);
            cS[q] += __shfl_xor_sync(0xffffffffu, cS[q], m);
        }
    if (lane < 4) {
#pragma unroll
        for (int q = 0; q < 16; q++) {
            int gj = j0 + wn * 64 + (q >> 1) * 8 + 2 * lane + (q & 1);
            atomicAdd(&g_colZ[gj], cZ[q]);
            atomicAdd(&g_colS[gj], cS[q]);
        }
    }
}

// ---------------- launch 4: final reduction ----------------
__global__ void k_final(float* __restrict__ out) {
    int tid = threadIdx.x;
    float sum = 0.f;
    for (int i = tid; i < NROWS; i += 1024) {
        int l = g_lab[i];
        float inv = (l < 0) ? 1.f : 1.f / (float)g_hist[l & 1023];
        sum += logf(g_rowZ[i]) + logf(g_colZ[i]) - (g_rowS[i] + g_colS[i]) * inv;
    }
#pragma unroll
    for (int m = 16; m; m >>= 1) sum += __shfl_xor_sync(0xffffffffu, sum, m);
    __shared__ float ws[32];
    if ((tid & 31) == 0) ws[tid >> 5] = sum;
    __syncthreads();
    if (tid < 32) {
        float v = ws[tid];
#pragma unroll
        for (int m = 16; m; m >>= 1) v += __shfl_xor_sync(0xffffffffu, v, m);
        if (tid == 0) out[0] = v / (2.0f * NROWS);
    }
}

// ---------------- launch ----------------
extern "C" void kernel_launch(void* const* d_in, const int* in_sizes, int n_in,
                              void* d_out, int out_size) {
    const float* txt = (const float*)d_in[0];
    const float* img = (const float*)d_in[1];
    const void*  lab = d_in[2];

    cudaFuncSetAttribute(k_gemm, cudaFuncAttributeMaxDynamicSharedMemorySize,
                         2 * STAGE_BYTES);

    k_detect<<<1, 256>>>((const int*)lab);            // launch 0
    k_init<<<32, 256>>>(lab);                         // launch 1 (labels+hist+zero)
    k_norm<<<2 * NROWS, 128>>>(img, txt);             // launch 2
    dim3 grid(32, 64);
    k_gemm<<<grid, 256, 2 * STAGE_BYTES>>>();         // launch 3  <- ncu -s captures here
    k_final<<<1, 1024>>>((float*)d_out);              // launch 4
}

// round 11
// speedup vs baseline: 1.1317x; 1.0143x over previous
#include <cuda_runtime.h>
#include <cuda_fp16.h>
#include <math.h>
#include <stdint.h>

#define NROWS 8192
#define DIM 512
#define LOGIT_SCALE 2.659f
#define QSCALE 16.0f          // feature pre-scale before e4m3 quantization
#define INV_QS2 (1.0f / (QSCALE * QSCALE))

// ---------------- device scratch ----------------
__device__ uint8_t g_A8[NROWS * DIM];   // normalized image features (e4m3, x16)
__device__ uint8_t g_B8[NROWS * DIM];   // normalized text features (e4m3, x16)
__device__ float g_rowZ[NROWS], g_rowS[NROWS], g_colZ[NROWS], g_colS[NROWS];
__device__ int   g_lab[NROWS];
__device__ int   g_hist[1024];          // zeroed by k_final after use (graph-replay safe)

// ---------------- fast exp on the FMA pipe (|x| <= ~3, rel err ~2e-6) ----------------
__device__ __forceinline__ float fexp(float s) {
    float t = s * 1.4426950408889634f;
    float z = t + 12582912.0f;
    int   n = __float_as_int(z) - 0x4B400000;
    float nf = z - 12582912.0f;
    float f = t - nf;
    float p = 1.3333558146e-3f;
    p = fmaf(p, f, 9.6181291076e-3f);
    p = fmaf(p, f, 5.5504108665e-2f);
    p = fmaf(p, f, 2.4022650696e-1f);
    p = fmaf(p, f, 6.9314718056e-1f);
    p = fmaf(p, f, 1.0f);
    return __int_as_float(__float_as_int(p) + (n << 23));
}

// ---------------- async copy helpers ----------------
#define CP_ASYNC16(dst, src) \
    asm volatile("cp.async.cg.shared.global [%0], [%1], 16;" :: "r"(dst), "l"(src))
#define CP_COMMIT() asm volatile("cp.async.commit_group;" ::: "memory")
#define CP_WAIT(n)  asm volatile("cp.async.wait_group %0;" :: "n"(n) : "memory")

__device__ __forceinline__ uint32_t smem_u32(const void* p) {
    uint32_t a;
    asm("{ .reg .u64 t; cvta.to.shared.u64 t, %1; cvt.u32.u64 %0, t; }" : "=r"(a) : "l"(p));
    return a;
}

__device__ __forceinline__ void ldmatrix_x4(uint32_t& r0, uint32_t& r1, uint32_t& r2,
                                            uint32_t& r3, uint32_t addr) {
    asm volatile("ldmatrix.sync.aligned.m8n8.x4.shared.b16 {%0,%1,%2,%3}, [%4];"
                 : "=r"(r0), "=r"(r1), "=r"(r2), "=r"(r3) : "r"(addr));
}

// e4m3 x e4m3 -> f16 accumulate, m16n8k32 (acc: 2 regs of half2)
__device__ __forceinline__ void mma_fp8_f16(uint32_t* d, const uint32_t* a,
                                            uint32_t b0, uint32_t b1) {
    asm volatile(
        "mma.sync.aligned.m16n8k32.row.col.f16.e4m3.e4m3.f16 "
        "{%0,%1}, {%2,%3,%4,%5}, {%6,%7}, {%0,%1};"
        : "+r"(d[0]), "+r"(d[1])
        : "r"(a[0]), "r"(a[1]), "r"(a[2]), "r"(a[3]), "r"(b0), "r"(b1));
}

// pack two floats into two e4m3 bytes (hi, lo)
__device__ __forceinline__ uint16_t pack_e4m3x2(float hi, float lo) {
    uint16_t r;
    asm("cvt.rn.satfinite.e4m3x2.f32 %0, %1, %2;" : "=h"(r) : "f"(hi), "f"(lo));
    return r;
}

// ---------------- launch 0: labels (detect + decode + hist) + zero accumulators ----------------
// Each of the 32 blocks redundantly detects int64-vs-int32 over the first 8192
// words (in-bounds under both interpretations), avoiding a separate kernel.
__global__ void k_init(const int* __restrict__ w) {
    __shared__ int s_is64;
    int ok = 1;
    for (int p = threadIdx.x; p < 4096; p += 256) {
        int lo = w[2 * p], hi = w[2 * p + 1];
        if (hi != (lo >> 31)) ok = 0;
    }
    ok = __syncthreads_and(ok);
    if (threadIdx.x == 0) s_is64 = ok;
    __syncthreads();
    int i = blockIdx.x * 256 + threadIdx.x;
    int lab = s_is64 ? (int)((const long long*)w)[i] : w[i];
    g_lab[i] = lab;
    if (lab >= 0) atomicAdd(&g_hist[lab & 1023], 1);
    g_rowZ[i] = 0.f; g_rowS[i] = 0.f;
    g_colZ[i] = 0.f; g_colS[i] = 0.f;
}

// ---------------- launch 1: normalize + scale + cast to e4m3 ----------------
// One warp per row; each lane loads 4 consecutive float4 (MLP=4), warp-shuffle
// reduction only (no smem/barrier), one 16B store of e4m3 per lane.
__global__ void k_norm(const float* __restrict__ img, const float* __restrict__ txt) {
    int wgl = blockIdx.x * 8 + (threadIdx.x >> 5);   // global warp id: 0..16383
    int lane = threadIdx.x & 31;
    const float* src; uint8_t* dst; int row;
    if (wgl < NROWS) { src = img; dst = g_A8; row = wgl; }
    else             { src = txt; dst = g_B8; row = wgl - NROWS; }
    const float4* p = (const float4*)(src + (size_t)row * DIM) + lane * 4;
    float4 v0 = p[0], v1 = p[1], v2 = p[2], v3 = p[3];
    float ss = v0.x * v0.x + v0.y * v0.y + v0.z * v0.z + v0.w * v0.w
             + v1.x * v1.x + v1.y * v1.y + v1.z * v1.z + v1.w * v1.w
             + v2.x * v2.x + v2.y * v2.y + v2.z * v2.z + v2.w * v2.w
             + v3.x * v3.x + v3.y * v3.y + v3.z * v3.z + v3.w * v3.w;
#pragma unroll
    for (int m = 16; m; m >>= 1) ss += __shfl_xor_sync(0xffffffffu, ss, m);
    float inv = QSCALE * rsqrtf(fmaxf(ss, 1e-24f));
    uint4 o;
    o.x = (uint32_t)pack_e4m3x2(v0.y * inv, v0.x * inv)
        | ((uint32_t)pack_e4m3x2(v0.w * inv, v0.z * inv) << 16);
    o.y = (uint32_t)pack_e4m3x2(v1.y * inv, v1.x * inv)
        | ((uint32_t)pack_e4m3x2(v1.w * inv, v1.z * inv) << 16);
    o.z = (uint32_t)pack_e4m3x2(v2.y * inv, v2.x * inv)
        | ((uint32_t)pack_e4m3x2(v2.w * inv, v2.z * inv) << 16);
    o.w = (uint32_t)pack_e4m3x2(v3.y * inv, v3.x * inv)
        | ((uint32_t)pack_e4m3x2(v3.w * inv, v3.z * inv) << 16);
    *(uint4*)(dst + (size_t)row * DIM + lane * 16) = o;
}

// ---------------- launch 2: fused fp8 GEMM (f16 acc) + softmax-stat epilogue ----------------
// CTA tile 128(m) x 256(n), BK=128 bytes, 2-stage double buffer, 4 mainloop
// iterations, one barrier per iteration. 8 warps in 2(m) x 4(n) grid -> warp
// tile 64x64, fp16 accumulators, explicit B-fragment double buffering.
// 2 CTAs/SM (96KB smem each). Smem: 8-row x 16B blocked tiles:
//   off(r,c) = ((r>>3)*8 + (c>>4))*128 + (r&7)*16      (ldmatrix.x4-friendly)
#define STAGE_BYTES 49152

__global__ __launch_bounds__(256, 2) void k_gemm() {
    extern __shared__ char smem[];
    const uint32_t sbase = smem_u32(smem);
    const int tid = threadIdx.x;
    const int lane = tid & 31, wid = tid >> 5;
    const int wm = wid & 1, wn = wid >> 1;            // 2 x 4 warp grid
    const int i0 = blockIdx.y * 128, j0 = blockIdx.x * 256;

    const int g = lane >> 3;         // lane group 0..3
    const int lr = lane & 7;
    const uint32_t aBase = (uint32_t)(wm * 8192 + (g & 1) * 1024 + (g >> 1) * 128 + lr * 16);
    const uint32_t bBase = (uint32_t)(16384 + wn * 8192 + (g >> 1) * 1024 + (g & 1) * 128 + lr * 16);

    // loader: 256 threads; A 1024 vec16 (4/thread), B 2048 vec16 (8/thread)
    const int r0  = tid >> 3;        // 0..31
    const int seg = tid & 7;         // 16B chunk within the 128B stage row
    const uint32_t dBase = (uint32_t)(((r0 >> 3) * 8 + seg) * 128 + (r0 & 7) * 16);
    const uint8_t* pA = g_A8 + (size_t)(i0 + r0) * DIM + seg * 16;
    const uint8_t* pB = g_B8 + (size_t)(j0 + r0) * DIM + seg * 16;

    uint32_t acc[4][8][2];   // f16 accumulators (half2 pairs), warp tile 64x64
#pragma unroll
    for (int mt = 0; mt < 4; mt++)
#pragma unroll
        for (int nt = 0; nt < 8; nt++) { acc[mt][nt][0] = 0u; acc[mt][nt][1] = 0u; }

    auto load_stage = [&](int s, int kk) {
        uint32_t sA = sbase + s * STAGE_BYTES;
        uint32_t sB = sA + 16384;
#pragma unroll
        for (int t = 0; t < 4; t++)
            CP_ASYNC16(sA + dBase + t * 4096, pA + (size_t)(32 * t) * DIM + kk);
#pragma unroll
        for (int t = 0; t < 8; t++)
            CP_ASYNC16(sB + dBase + t * 4096, pB + (size_t)(32 * t) * DIM + kk);
    };

    load_stage(0, 0);
    CP_COMMIT();

    for (int it = 0; it < 4; it++) {
        CP_WAIT(0);
        __syncthreads();
        if (it + 1 < 4) {
            load_stage((it + 1) & 1, (it + 1) * 128);
            CP_COMMIT();
        }
        uint32_t stg = sbase + (it & 1) * STAGE_BYTES;
#pragma unroll
        for (int ks = 0; ks < 4; ks++) {
            uint32_t A[4][4];
#pragma unroll
            for (int mt = 0; mt < 4; mt++)
                ldmatrix_x4(A[mt][0], A[mt][1], A[mt][2], A[mt][3],
                            stg + aBase + mt * 2048 + ks * 256);
            // B double buffer: prefetch np+1 before np's QMMA block
            uint32_t Bc[4], Bn[4];
            ldmatrix_x4(Bc[0], Bc[1], Bc[2], Bc[3], stg + bBase + ks * 256);
#pragma unroll
            for (int np = 0; np < 4; np++) {
                if (np < 3)
                    ldmatrix_x4(Bn[0], Bn[1], Bn[2], Bn[3],
                                stg + bBase + (np + 1) * 2048 + ks * 256);
#pragma unroll
                for (int mt = 0; mt < 4; mt++) {
                    mma_fp8_f16(acc[mt][np * 2],     A[mt], Bc[0], Bc[1]);
                    mma_fp8_f16(acc[mt][np * 2 + 1], A[mt], Bc[2], Bc[3]);
                }
#pragma unroll
                for (int q = 0; q < 4; q++) Bc[q] = Bn[q];
            }
        }
    }

    // ---- epilogue: logits -> exp + target-weighted stats (registers only) ----
    const int r_base = i0 + wm * 64 + (lane >> 2);
    const int c_base = j0 + wn * 64 + 2 * (lane & 3);
    const float lsc = LOGIT_SCALE * INV_QS2;

    int labR[8];
#pragma unroll
    for (int q = 0; q < 8; q++) labR[q] = g_lab[r_base + (q >> 1) * 16 + (q & 1) * 8];
    int labC[16];
#pragma unroll
    for (int nt = 0; nt < 8; nt++) {
        labC[nt * 2]     = g_lab[c_base + nt * 8];
        labC[nt * 2 + 1] = g_lab[c_base + nt * 8 + 1];
    }

    float rZ[8], rS[8], cZ[16], cS[16];
#pragma unroll
    for (int q = 0; q < 8; q++) { rZ[q] = 0.f; rS[q] = 0.f; }
#pragma unroll
    for (int q = 0; q < 16; q++) { cZ[q] = 0.f; cS[q] = 0.f; }

#pragma unroll
    for (int mt = 0; mt < 4; mt++)
#pragma unroll
        for (int nt = 0; nt < 8; nt++)
#pragma unroll
            for (int hb = 0; hb < 2; hb++) {
                float2 pv = __half22float2(*(__half2*)&acc[mt][nt][hb]);
                int gi = r_base + mt * 16 + hb * 8;
                int li = labR[mt * 2 + hb];
#pragma unroll
                for (int d = 0; d < 2; d++) {
                    float sv = lsc * (d ? pv.y : pv.x);
                    float ex = fexp(sv);
                    int gj = c_base + nt * 8 + d;
                    bool tg = (gi == gj) || (li >= 0 && li == labC[nt * 2 + d]);
                    float ms = tg ? sv : 0.f;
                    rZ[mt * 2 + hb] += ex; rS[mt * 2 + hb] += ms;
                    cZ[nt * 2 + d] += ex;  cS[nt * 2 + d] += ms;
                }
            }

    // rows: reduce across the 4 lanes of each quad
#pragma unroll
    for (int m = 1; m <= 2; m <<= 1)
#pragma unroll
        for (int q = 0; q < 8; q++) {
            rZ[q] += __shfl_xor_sync(0xffffffffu, rZ[q], m);
            rS[q] += __shfl_xor_sync(0xffffffffu, rS[q], m);
        }
    if ((lane & 3) == 0) {
#pragma unroll
        for (int q = 0; q < 8; q++) {
            int gi = r_base + (q >> 1) * 16 + (q & 1) * 8;
            atomicAdd(&g_rowZ[gi], rZ[q]);
            atomicAdd(&g_rowS[gi], rS[q]);
        }
    }

    // cols: reduce across lane>>2
#pragma unroll
    for (int m = 4; m <= 16; m <<= 1)
#pragma unroll
        for (int q = 0; q < 16; q++) {
            cZ[q] += __shfl_xor_sync(0xffffffffu, cZ[q], m);
            cS[q] += __shfl_xor_sync(0xffffffffu, cS[q], m);
        }
    if (lane < 4) {
#pragma unroll
        for (int q = 0; q < 16; q++) {
            int gj = j0 + wn * 64 + (q >> 1) * 8 + 2 * lane + (q & 1);
            atomicAdd(&g_colZ[gj], cZ[q]);
            atomicAdd(&g_colS[gj], cS[q]);
        }
    }
}

// ---------------- launch 3: final reduction (+ hist re-zero for graph replay) ----------------
__global__ void k_final(float* __restrict__ out) {
    int tid = threadIdx.x;
    float sum = 0.f;
    for (int i = tid; i < NROWS; i += 1024) {
        int l = g_lab[i];
        float inv = (l < 0) ? 1.f : 1.f / (float)g_hist[l & 1023];
        sum += logf(g_rowZ[i]) + logf(g_colZ[i]) - (g_rowS[i] + g_colS[i]) * inv;
    }
#pragma unroll
    for (int m = 16; m; m >>= 1) sum += __shfl_xor_sync(0xffffffffu, sum, m);
    __shared__ float ws[32];
    if ((tid & 31) == 0) ws[tid >> 5] = sum;
    __syncthreads();
    if (tid < 32) {
        float v = ws[tid];
#pragma unroll
        for (int m = 16; m; m >>= 1) v += __shfl_xor_sync(0xffffffffu, v, m);
        if (tid == 0) out[0] = v / (2.0f * NROWS);
    }
    __syncthreads();
    if (tid < 1024) { if (tid < 1024 && tid < 1024) { } }
    for (int i = tid; i < 1024; i += 1024) g_hist[i] = 0;   // reset for next replay
}

// ---------------- launch ----------------
extern "C" void kernel_launch(void* const* d_in, const int* in_sizes, int n_in,
                              void* d_out, int out_size) {
    const float* txt = (const float*)d_in[0];
    const float* img = (const float*)d_in[1];
    const void*  lab = d_in[2];

    cudaFuncSetAttribute(k_gemm, cudaFuncAttributeMaxDynamicSharedMemorySize,
                         2 * STAGE_BYTES);

    k_init<<<32, 256>>>((const int*)lab);             // launch 0 (detect+labels+hist+zero)
    k_norm<<<2048, 256>>>(img, txt);                  // launch 1 (warp-per-row)
    dim3 grid(32, 64);
    k_gemm<<<grid, 256, 2 * STAGE_BYTES>>>();         // launch 2
    k_final<<<1, 1024>>>((float*)d_out);              // launch 3
}

// round 12
// speedup vs baseline: 1.1641x; 1.0287x over previous
#include <cuda_runtime.h>
#include <cuda_fp16.h>
#include <math.h>
#include <stdint.h>

#define NROWS 8192
#define DIM 512
#define LOGIT_SCALE 2.659f
#define QSCALE 16.0f          // feature pre-scale before e4m3 quantization
#define INV_QS2 (1.0f / (QSCALE * QSCALE))

// ---------------- device scratch ----------------
__device__ uint8_t g_A8[NROWS * DIM];   // normalized image features (e4m3, x16)
__device__ uint8_t g_B8[NROWS * DIM];   // normalized text features (e4m3, x16)
__device__ float g_rowZ[NROWS], g_rowS[NROWS], g_colZ[NROWS], g_colS[NROWS];
__device__ int   g_lab[NROWS];
__device__ int   g_hist[1024];          // reset by k_out (graph-replay safe)
__device__ int   g_rc[64];              // per-i-tile-row completion counters
__device__ int   g_cc[32];              // per-j-tile-col completion counters
__device__ float g_loss;                // accumulated total loss (reset by k_out)

// ---------------- fast exp on the FMA pipe (|x| <= ~3, rel err ~2e-6) ----------------
__device__ __forceinline__ float fexp(float s) {
    float t = s * 1.4426950408889634f;
    float z = t + 12582912.0f;
    int   n = __float_as_int(z) - 0x4B400000;
    float nf = z - 12582912.0f;
    float f = t - nf;
    float p = 1.3333558146e-3f;
    p = fmaf(p, f, 9.6181291076e-3f);
    p = fmaf(p, f, 5.5504108665e-2f);
    p = fmaf(p, f, 2.4022650696e-1f);
    p = fmaf(p, f, 6.9314718056e-1f);
    p = fmaf(p, f, 1.0f);
    return __int_as_float(__float_as_int(p) + (n << 23));
}

// ---------------- async copy helpers ----------------
#define CP_ASYNC16(dst, src) \
    asm volatile("cp.async.cg.shared.global [%0], [%1], 16;" :: "r"(dst), "l"(src))
#define CP_COMMIT() asm volatile("cp.async.commit_group;" ::: "memory")
#define CP_WAIT(n)  asm volatile("cp.async.wait_group %0;" :: "n"(n) : "memory")

__device__ __forceinline__ uint32_t smem_u32(const void* p) {
    uint32_t a;
    asm("{ .reg .u64 t; cvta.to.shared.u64 t, %1; cvt.u32.u64 %0, t; }" : "=r"(a) : "l"(p));
    return a;
}

__device__ __forceinline__ void ldmatrix_x4(uint32_t& r0, uint32_t& r1, uint32_t& r2,
                                            uint32_t& r3, uint32_t addr) {
    asm volatile("ldmatrix.sync.aligned.m8n8.x4.shared.b16 {%0,%1,%2,%3}, [%4];"
                 : "=r"(r0), "=r"(r1), "=r"(r2), "=r"(r3) : "r"(addr));
}

// e4m3 x e4m3 -> f16 accumulate, m16n8k32 (acc: 2 regs of half2)
__device__ __forceinline__ void mma_fp8_f16(uint32_t* d, const uint32_t* a,
                                            uint32_t b0, uint32_t b1) {
    asm volatile(
        "mma.sync.aligned.m16n8k32.row.col.f16.e4m3.e4m3.f16 "
        "{%0,%1}, {%2,%3,%4,%5}, {%6,%7}, {%0,%1};"
        : "+r"(d[0]), "+r"(d[1])
        : "r"(a[0]), "r"(a[1]), "r"(a[2]), "r"(a[3]), "r"(b0), "r"(b1));
}

// pack two floats into two e4m3 bytes (hi, lo)
__device__ __forceinline__ uint16_t pack_e4m3x2(float hi, float lo) {
    uint16_t r;
    asm("cvt.rn.satfinite.e4m3x2.f32 %0, %1, %2;" : "=h"(r) : "f"(hi), "f"(lo));
    return r;
}

// ---------------- launch 0: labels (detect + decode + hist) + zero accumulators ----------------
__global__ void k_init(const int* __restrict__ w) {
    __shared__ int s_is64;
    int ok = 1;
    for (int p = threadIdx.x; p < 4096; p += 256) {
        int lo = w[2 * p], hi = w[2 * p + 1];
        if (hi != (lo >> 31)) ok = 0;
    }
    ok = __syncthreads_and(ok);
    if (threadIdx.x == 0) s_is64 = ok;
    __syncthreads();
    int i = blockIdx.x * 256 + threadIdx.x;
    int lab = s_is64 ? (int)((const long long*)w)[i] : w[i];
    g_lab[i] = lab;
    if (lab >= 0) atomicAdd(&g_hist[lab & 1023], 1);
    g_rowZ[i] = 0.f; g_rowS[i] = 0.f;
    g_colZ[i] = 0.f; g_colS[i] = 0.f;
}

// ---------------- launch 1: normalize + scale + cast to e4m3 ----------------
__global__ void k_norm(const float* __restrict__ img, const float* __restrict__ txt) {
    int wgl = blockIdx.x * 8 + (threadIdx.x >> 5);   // global warp id: 0..16383
    int lane = threadIdx.x & 31;
    const float* src; uint8_t* dst; int row;
    if (wgl < NROWS) { src = img; dst = g_A8; row = wgl; }
    else             { src = txt; dst = g_B8; row = wgl - NROWS; }
    const float4* p = (const float4*)(src + (size_t)row * DIM) + lane * 4;
    float4 v0 = p[0], v1 = p[1], v2 = p[2], v3 = p[3];
    float ss = v0.x * v0.x + v0.y * v0.y + v0.z * v0.z + v0.w * v0.w
             + v1.x * v1.x + v1.y * v1.y + v1.z * v1.z + v1.w * v1.w
             + v2.x * v2.x + v2.y * v2.y + v2.z * v2.z + v2.w * v2.w
             + v3.x * v3.x + v3.y * v3.y + v3.z * v3.z + v3.w * v3.w;
#pragma unroll
    for (int m = 16; m; m >>= 1) ss += __shfl_xor_sync(0xffffffffu, ss, m);
    float inv = QSCALE * rsqrtf(fmaxf(ss, 1e-24f));
    uint4 o;
    o.x = (uint32_t)pack_e4m3x2(v0.y * inv, v0.x * inv)
        | ((uint32_t)pack_e4m3x2(v0.w * inv, v0.z * inv) << 16);
    o.y = (uint32_t)pack_e4m3x2(v1.y * inv, v1.x * inv)
        | ((uint32_t)pack_e4m3x2(v1.w * inv, v1.z * inv) << 16);
    o.z = (uint32_t)pack_e4m3x2(v2.y * inv, v2.x * inv)
        | ((uint32_t)pack_e4m3x2(v2.w * inv, v2.z * inv) << 16);
    o.w = (uint32_t)pack_e4m3x2(v3.y * inv, v3.x * inv)
        | ((uint32_t)pack_e4m3x2(v3.w * inv, v3.z * inv) << 16);
    *(uint4*)(dst + (size_t)row * DIM + lane * 16) = o;
}

// ---------------- launch 2: fused fp8 GEMM + stats + distributed final reduce ----------------
// CTA tile 128(m) x 256(n), BK=128 bytes, 2-stage double buffer, 4 iterations.
// 8 warps (2m x 4n), warp tile 64x64, fp16 acc. 2 CTAs/SM (96KB smem).
// After epilogue: per-tile-row (32 arrivals) / per-tile-col (64 arrivals)
// counters; the last CTA of each group reduces its slice of the final loss
// into g_loss, overlapped with the remaining grid.
#define STAGE_BYTES 49152

__global__ __launch_bounds__(256, 2) void k_gemm() {
    extern __shared__ char smem[];
    const uint32_t sbase = smem_u32(smem);
    const int tid = threadIdx.x;
    const int lane = tid & 31, wid = tid >> 5;
    const int wm = wid & 1, wn = wid >> 1;            // 2 x 4 warp grid
    const int i0 = blockIdx.y * 128, j0 = blockIdx.x * 256;

    const int g = lane >> 3;         // lane group 0..3
    const int lr = lane & 7;
    const uint32_t aBase = (uint32_t)(wm * 8192 + (g & 1) * 1024 + (g >> 1) * 128 + lr * 16);
    const uint32_t bBase = (uint32_t)(16384 + wn * 8192 + (g >> 1) * 1024 + (g & 1) * 128 + lr * 16);

    // loader: 256 threads; A 1024 vec16 (4/thread), B 2048 vec16 (8/thread)
    const int r0  = tid >> 3;        // 0..31
    const int seg = tid & 7;         // 16B chunk within the 128B stage row
    const uint32_t dBase = (uint32_t)(((r0 >> 3) * 8 + seg) * 128 + (r0 & 7) * 16);
    const uint8_t* pA = g_A8 + (size_t)(i0 + r0) * DIM + seg * 16;
    const uint8_t* pB = g_B8 + (size_t)(j0 + r0) * DIM + seg * 16;

    uint32_t acc[4][8][2];   // f16 accumulators (half2 pairs), warp tile 64x64
#pragma unroll
    for (int mt = 0; mt < 4; mt++)
#pragma unroll
        for (int nt = 0; nt < 8; nt++) { acc[mt][nt][0] = 0u; acc[mt][nt][1] = 0u; }

    auto load_stage = [&](int s, int kk) {
        uint32_t sA = sbase + s * STAGE_BYTES;
        uint32_t sB = sA + 16384;
#pragma unroll
        for (int t = 0; t < 4; t++)
            CP_ASYNC16(sA + dBase + t * 4096, pA + (size_t)(32 * t) * DIM + kk);
#pragma unroll
        for (int t = 0; t < 8; t++)
            CP_ASYNC16(sB + dBase + t * 4096, pB + (size_t)(32 * t) * DIM + kk);
    };

    load_stage(0, 0);
    CP_COMMIT();

    for (int it = 0; it < 4; it++) {
        CP_WAIT(0);
        __syncthreads();
        if (it + 1 < 4) {
            load_stage((it + 1) & 1, (it + 1) * 128);
            CP_COMMIT();
        }
        uint32_t stg = sbase + (it & 1) * STAGE_BYTES;
#pragma unroll
        for (int ks = 0; ks < 4; ks++) {
            uint32_t A[4][4];
#pragma unroll
            for (int mt = 0; mt < 4; mt++)
                ldmatrix_x4(A[mt][0], A[mt][1], A[mt][2], A[mt][3],
                            stg + aBase + mt * 2048 + ks * 256);
            uint32_t Bc[4], Bn[4];
            ldmatrix_x4(Bc[0], Bc[1], Bc[2], Bc[3], stg + bBase + ks * 256);
#pragma unroll
            for (int np = 0; np < 4; np++) {
                if (np < 3)
                    ldmatrix_x4(Bn[0], Bn[1], Bn[2], Bn[3],
                                stg + bBase + (np + 1) * 2048 + ks * 256);
#pragma unroll
                for (int mt = 0; mt < 4; mt++) {
                    mma_fp8_f16(acc[mt][np * 2],     A[mt], Bc[0], Bc[1]);
                    mma_fp8_f16(acc[mt][np * 2 + 1], A[mt], Bc[2], Bc[3]);
                }
#pragma unroll
                for (int q = 0; q < 4; q++) Bc[q] = Bn[q];
            }
        }
    }

    // ---- epilogue: logits -> exp + target-weighted stats (registers only) ----
    const int r_base = i0 + wm * 64 + (lane >> 2);
    const int c_base = j0 + wn * 64 + 2 * (lane & 3);
    const float lsc = LOGIT_SCALE * INV_QS2;

    int labR[8];
#pragma unroll
    for (int q = 0; q < 8; q++) labR[q] = g_lab[r_base + (q >> 1) * 16 + (q & 1) * 8];
    int labC[16];
#pragma unroll
    for (int nt = 0; nt < 8; nt++) {
        labC[nt * 2]     = g_lab[c_base + nt * 8];
        labC[nt * 2 + 1] = g_lab[c_base + nt * 8 + 1];
    }

    float rZ[8], rS[8], cZ[16], cS[16];
#pragma unroll
    for (int q = 0; q < 8; q++) { rZ[q] = 0.f; rS[q] = 0.f; }
#pragma unroll
    for (int q = 0; q < 16; q++) { cZ[q] = 0.f; cS[q] = 0.f; }

#pragma unroll
    for (int mt = 0; mt < 4; mt++)
#pragma unroll
        for (int nt = 0; nt < 8; nt++)
#pragma unroll
            for (int hb = 0; hb < 2; hb++) {
                float2 pv = __half22float2(*(__half2*)&acc[mt][nt][hb]);
                int gi = r_base + mt * 16 + hb * 8;
                int li = labR[mt * 2 + hb];
#pragma unroll
                for (int d = 0; d < 2; d++) {
                    float sv = lsc * (d ? pv.y : pv.x);
                    float ex = fexp(sv);
                    int gj = c_base + nt * 8 + d;
                    bool tg = (gi == gj) || (li >= 0 && li == labC[nt * 2 + d]);
                    float ms = tg ? sv : 0.f;
                    rZ[mt * 2 + hb] += ex; rS[mt * 2 + hb] += ms;
                    cZ[nt * 2 + d] += ex;  cS[nt * 2 + d] += ms;
                }
            }

    // rows: reduce across the 4 lanes of each quad
#pragma unroll
    for (int m = 1; m <= 2; m <<= 1)
#pragma unroll
        for (int q = 0; q < 8; q++) {
            rZ[q] += __shfl_xor_sync(0xffffffffu, rZ[q], m);
            rS[q] += __shfl_xor_sync(0xffffffffu, rS[q], m);
        }
    if ((lane & 3) == 0) {
#pragma unroll
        for (int q = 0; q < 8; q++) {
            int gi = r_base + (q >> 1) * 16 + (q & 1) * 8;
            atomicAdd(&g_rowZ[gi], rZ[q]);
            atomicAdd(&g_rowS[gi], rS[q]);
        }
    }

    // cols: reduce across lane>>2
#pragma unroll
    for (int m = 4; m <= 16; m <<= 1)
#pragma unroll
        for (int q = 0; q < 16; q++) {
            cZ[q] += __shfl_xor_sync(0xffffffffu, cZ[q], m);
            cS[q] += __shfl_xor_sync(0xffffffffu, cS[q], m);
        }
    if (lane < 4) {
#pragma unroll
        for (int q = 0; q < 16; q++) {
            int gj = j0 + wn * 64 + (q >> 1) * 8 + 2 * lane + (q & 1);
            atomicAdd(&g_colZ[gj], cZ[q]);
            atomicAdd(&g_colS[gj], cS[q]);
        }
    }

    // ---- distributed final reduction ----
    __threadfence();          // make this thread's atomics visible device-wide
    __syncthreads();          // all threads of this CTA have fenced
    __shared__ int fR, fC;
    if (tid == 0) {
        fR = (atomicAdd(&g_rc[blockIdx.y], 1) == 31);   // last of 32 j-tiles
        fC = (atomicAdd(&g_cc[blockIdx.x], 1) == 63);   // last of 64 i-tiles
    }
    __syncthreads();

    if (fR) {                 // rows i0..i0+127 complete: reduce row losses
        __threadfence();
        float part = 0.f;
        if (tid < 128) {
            int i = i0 + tid;
            int l = g_lab[i];
            float inv = (l < 0) ? 1.f : 1.f / (float)g_hist[l & 1023];
            part = logf(__ldcg(&g_rowZ[i])) - __ldcg(&g_rowS[i]) * inv;
        }
#pragma unroll
        for (int m = 16; m; m >>= 1) part += __shfl_xor_sync(0xffffffffu, part, m);
        if (lane == 0 && wid < 4) atomicAdd(&g_loss, part);
    }
    if (fC) {                 // cols j0..j0+255 complete: reduce col losses
        __threadfence();
        int j = j0 + tid;
        int l = g_lab[j];
        float inv = (l < 0) ? 1.f : 1.f / (float)g_hist[l & 1023];
        float part = logf(__ldcg(&g_colZ[j])) - __ldcg(&g_colS[j]) * inv;
#pragma unroll
        for (int m = 16; m; m >>= 1) part += __shfl_xor_sync(0xffffffffu, part, m);
        if (lane == 0) atomicAdd(&g_loss, part);
    }
}

// ---------------- launch 3: emit result + reset state for graph replay ----------------
__global__ void k_out(float* __restrict__ out) {
    int tid = threadIdx.x;   // 128 threads
    if (tid == 0) {
        out[0] = g_loss / (2.0f * NROWS);
        g_loss = 0.f;
    }
    if (tid < 64) g_rc[tid] = 0;
    if (tid < 32) g_cc[tid] = 0;
    for (int i = tid; i < 1024; i += 128) g_hist[i] = 0;
}

// ---------------- launch ----------------
extern "C" void kernel_launch(void* const* d_in, const int* in_sizes, int n_in,
                              void* d_out, int out_size) {
    const float* txt = (const float*)d_in[0];
    const float* img = (const float*)d_in[1];
    const void*  lab = d_in[2];

    cudaFuncSetAttribute(k_gemm, cudaFuncAttributeMaxDynamicSharedMemorySize,
                         2 * STAGE_BYTES);

    k_init<<<32, 256>>>((const int*)lab);             // launch 0
    k_norm<<<2048, 256>>>(img, txt);                  // launch 1
    dim3 grid(32, 64);
    k_gemm<<<grid, 256, 2 * STAGE_BYTES>>>();         // launch 2 (+ distributed reduce)
    k_out<<<1, 128>>>((float*)d_out);                 // launch 3 (tiny)
}

// round 13
// speedup vs baseline: 1.1742x; 1.0086x over previous
#include <cuda_runtime.h>
#include <cuda_fp16.h>
#include <math.h>
#include <stdint.h>

#define NROWS 8192
#define DIM 512
#define LOGIT_SCALE 2.659f
#define QSCALE 16.0f          // feature pre-scale before e4m3 quantization
#define INV_QS2 (1.0f / (QSCALE * QSCALE))

// ---------------- device scratch ----------------
__device__ uint8_t g_A8[NROWS * DIM];   // normalized image features (e4m3, x16)
__device__ uint8_t g_B8[NROWS * DIM];   // normalized text features (e4m3, x16)
__device__ float g_rowZ[NROWS], g_rowS[NROWS], g_colZ[NROWS], g_colS[NROWS];
__device__ int   g_lab[NROWS];
__device__ int   g_hist[1024];          // reset by last k_gemm CTA (replay safe)
__device__ int   g_rc[64];              // per-i-tile-row completion counters
__device__ int   g_cc[32];              // per-j-tile-col completion counters
__device__ int   g_done;                // global completion counter
__device__ float g_loss;                // accumulated total loss

// ---------------- fast exp on the FMA pipe (|x| <= ~3, rel err ~2e-6) ----------------
__device__ __forceinline__ float fexp(float s) {
    float t = s * 1.4426950408889634f;
    float z = t + 12582912.0f;
    int   n = __float_as_int(z) - 0x4B400000;
    float nf = z - 12582912.0f;
    float f = t - nf;
    float p = 1.3333558146e-3f;
    p = fmaf(p, f, 9.6181291076e-3f);
    p = fmaf(p, f, 5.5504108665e-2f);
    p = fmaf(p, f, 2.4022650696e-1f);
    p = fmaf(p, f, 6.9314718056e-1f);
    p = fmaf(p, f, 1.0f);
    return __int_as_float(__float_as_int(p) + (n << 23));
}

// ---------------- async copy helpers ----------------
#define CP_ASYNC16(dst, src) \
    asm volatile("cp.async.cg.shared.global [%0], [%1], 16;" :: "r"(dst), "l"(src))
#define CP_COMMIT() asm volatile("cp.async.commit_group;" ::: "memory")
#define CP_WAIT(n)  asm volatile("cp.async.wait_group %0;" :: "n"(n) : "memory")

__device__ __forceinline__ uint32_t smem_u32(const void* p) {
    uint32_t a;
    asm("{ .reg .u64 t; cvta.to.shared.u64 t, %1; cvt.u32.u64 %0, t; }" : "=r"(a) : "l"(p));
    return a;
}

__device__ __forceinline__ void ldmatrix_x4(uint32_t& r0, uint32_t& r1, uint32_t& r2,
                                            uint32_t& r3, uint32_t addr) {
    asm volatile("ldmatrix.sync.aligned.m8n8.x4.shared.b16 {%0,%1,%2,%3}, [%4];"
                 : "=r"(r0), "=r"(r1), "=r"(r2), "=r"(r3) : "r"(addr));
}

// e4m3 x e4m3 -> f16 accumulate, m16n8k32 (acc: 2 regs of half2)
__device__ __forceinline__ void mma_fp8_f16(uint32_t* d, const uint32_t* a,
                                            uint32_t b0, uint32_t b1) {
    asm volatile(
        "mma.sync.aligned.m16n8k32.row.col.f16.e4m3.e4m3.f16 "
        "{%0,%1}, {%2,%3,%4,%5}, {%6,%7}, {%0,%1};"
        : "+r"(d[0]), "+r"(d[1])
        : "r"(a[0]), "r"(a[1]), "r"(a[2]), "r"(a[3]), "r"(b0), "r"(b1));
}

// pack two floats into two e4m3 bytes (hi, lo)
__device__ __forceinline__ uint16_t pack_e4m3x2(float hi, float lo) {
    uint16_t r;
    asm("cvt.rn.satfinite.e4m3x2.f32 %0, %1, %2;" : "=h"(r) : "f"(hi), "f"(lo));
    return r;
}

// ---------------- launch 0: normalize/cast + (blocks 0..31) label init ----------------
// Blocks 0..31 additionally: detect int64-vs-int32 labels, decode, histogram,
// and zero the stat accumulators. All init completes before k_gemm launches.
__global__ void k_norm(const float* __restrict__ img, const float* __restrict__ txt,
                       const int* __restrict__ w) {
    if (blockIdx.x < 32) {
        __shared__ int s_is64;
        int ok = 1;
        for (int p = threadIdx.x; p < 4096; p += 256) {
            int lo = w[2 * p], hi = w[2 * p + 1];
            if (hi != (lo >> 31)) ok = 0;
        }
        ok = __syncthreads_and(ok);
        if (threadIdx.x == 0) s_is64 = ok;
        __syncthreads();
        int i = blockIdx.x * 256 + threadIdx.x;
        int lab = s_is64 ? (int)((const long long*)w)[i] : w[i];
        g_lab[i] = lab;
        if (lab >= 0) atomicAdd(&g_hist[lab & 1023], 1);
        g_rowZ[i] = 0.f; g_rowS[i] = 0.f;
        g_colZ[i] = 0.f; g_colS[i] = 0.f;
    }

    int wgl = blockIdx.x * 8 + (threadIdx.x >> 5);   // global warp id: 0..16383
    int lane = threadIdx.x & 31;
    const float* src; uint8_t* dst; int row;
    if (wgl < NROWS) { src = img; dst = g_A8; row = wgl; }
    else             { src = txt; dst = g_B8; row = wgl - NROWS; }
    const float4* p = (const float4*)(src + (size_t)row * DIM) + lane * 4;
    float4 v0 = p[0], v1 = p[1], v2 = p[2], v3 = p[3];
    float ss = v0.x * v0.x + v0.y * v0.y + v0.z * v0.z + v0.w * v0.w
             + v1.x * v1.x + v1.y * v1.y + v1.z * v1.z + v1.w * v1.w
             + v2.x * v2.x + v2.y * v2.y + v2.z * v2.z + v2.w * v2.w
             + v3.x * v3.x + v3.y * v3.y + v3.z * v3.z + v3.w * v3.w;
#pragma unroll
    for (int m = 16; m; m >>= 1) ss += __shfl_xor_sync(0xffffffffu, ss, m);
    float inv = QSCALE * rsqrtf(fmaxf(ss, 1e-24f));
    uint4 o;
    o.x = (uint32_t)pack_e4m3x2(v0.y * inv, v0.x * inv)
        | ((uint32_t)pack_e4m3x2(v0.w * inv, v0.z * inv) << 16);
    o.y = (uint32_t)pack_e4m3x2(v1.y * inv, v1.x * inv)
        | ((uint32_t)pack_e4m3x2(v1.w * inv, v1.z * inv) << 16);
    o.z = (uint32_t)pack_e4m3x2(v2.y * inv, v2.x * inv)
        | ((uint32_t)pack_e4m3x2(v2.w * inv, v2.z * inv) << 16);
    o.w = (uint32_t)pack_e4m3x2(v3.y * inv, v3.x * inv)
        | ((uint32_t)pack_e4m3x2(v3.w * inv, v3.z * inv) << 16);
    *(uint4*)(dst + (size_t)row * DIM + lane * 16) = o;
}

// ---------------- launch 1: fused fp8 GEMM + stats + distributed reduce + output ----------------
// CTA tile 128(m) x 256(n), BK=128 bytes, 2-stage double buffer, 4 iterations.
// 8 warps (2m x 4n), warp tile 64x64, fp16 acc. 2 CTAs/SM (96KB smem).
// Tail: group counters -> partial loss reduction; global counter -> the last
// CTA writes out[0] and resets all replay state.
#define STAGE_BYTES 49152

__global__ __launch_bounds__(256, 2) void k_gemm(float* __restrict__ out) {
    extern __shared__ char smem[];
    const uint32_t sbase = smem_u32(smem);
    const int tid = threadIdx.x;
    const int lane = tid & 31, wid = tid >> 5;
    const int wm = wid & 1, wn = wid >> 1;            // 2 x 4 warp grid
    const int i0 = blockIdx.y * 128, j0 = blockIdx.x * 256;

    const int g = lane >> 3;         // lane group 0..3
    const int lr = lane & 7;
    const uint32_t aBase = (uint32_t)(wm * 8192 + (g & 1) * 1024 + (g >> 1) * 128 + lr * 16);
    const uint32_t bBase = (uint32_t)(16384 + wn * 8192 + (g >> 1) * 1024 + (g & 1) * 128 + lr * 16);

    // loader: 256 threads; A 1024 vec16 (4/thread), B 2048 vec16 (8/thread)
    const int r0  = tid >> 3;        // 0..31
    const int seg = tid & 7;         // 16B chunk within the 128B stage row
    const uint32_t dBase = (uint32_t)(((r0 >> 3) * 8 + seg) * 128 + (r0 & 7) * 16);
    const uint8_t* pA = g_A8 + (size_t)(i0 + r0) * DIM + seg * 16;
    const uint8_t* pB = g_B8 + (size_t)(j0 + r0) * DIM + seg * 16;

    uint32_t acc[4][8][2];   // f16 accumulators (half2 pairs), warp tile 64x64
#pragma unroll
    for (int mt = 0; mt < 4; mt++)
#pragma unroll
        for (int nt = 0; nt < 8; nt++) { acc[mt][nt][0] = 0u; acc[mt][nt][1] = 0u; }

    auto load_stage = [&](int s, int kk) {
        uint32_t sA = sbase + s * STAGE_BYTES;
        uint32_t sB = sA + 16384;
#pragma unroll
        for (int t = 0; t < 4; t++)
            CP_ASYNC16(sA + dBase + t * 4096, pA + (size_t)(32 * t) * DIM + kk);
#pragma unroll
        for (int t = 0; t < 8; t++)
            CP_ASYNC16(sB + dBase + t * 4096, pB + (size_t)(32 * t) * DIM + kk);
    };

    load_stage(0, 0);
    CP_COMMIT();

    for (int it = 0; it < 4; it++) {
        CP_WAIT(0);
        __syncthreads();
        if (it + 1 < 4) {
            load_stage((it + 1) & 1, (it + 1) * 128);
            CP_COMMIT();
        }
        uint32_t stg = sbase + (it & 1) * STAGE_BYTES;
#pragma unroll
        for (int ks = 0; ks < 4; ks++) {
            uint32_t A[4][4];
#pragma unroll
            for (int mt = 0; mt < 4; mt++)
                ldmatrix_x4(A[mt][0], A[mt][1], A[mt][2], A[mt][3],
                            stg + aBase + mt * 2048 + ks * 256);
            uint32_t Bc[4], Bn[4];
            ldmatrix_x4(Bc[0], Bc[1], Bc[2], Bc[3], stg + bBase + ks * 256);
#pragma unroll
            for (int np = 0; np < 4; np++) {
                if (np < 3)
                    ldmatrix_x4(Bn[0], Bn[1], Bn[2], Bn[3],
                                stg + bBase + (np + 1) * 2048 + ks * 256);
#pragma unroll
                for (int mt = 0; mt < 4; mt++) {
                    mma_fp8_f16(acc[mt][np * 2],     A[mt], Bc[0], Bc[1]);
                    mma_fp8_f16(acc[mt][np * 2 + 1], A[mt], Bc[2], Bc[3]);
                }
#pragma unroll
                for (int q = 0; q < 4; q++) Bc[q] = Bn[q];
            }
        }
    }

    // ---- epilogue: logits -> exp + target-weighted stats (registers only) ----
    const int r_base = i0 + wm * 64 + (lane >> 2);
    const int c_base = j0 + wn * 64 + 2 * (lane & 3);
    const float lsc = LOGIT_SCALE * INV_QS2;

    int labR[8];
#pragma unroll
    for (int q = 0; q < 8; q++) labR[q] = g_lab[r_base + (q >> 1) * 16 + (q & 1) * 8];
    int labC[16];
#pragma unroll
    for (int nt = 0; nt < 8; nt++) {
        labC[nt * 2]     = g_lab[c_base + nt * 8];
        labC[nt * 2 + 1] = g_lab[c_base + nt * 8 + 1];
    }

    float rZ[8], rS[8], cZ[16], cS[16];
#pragma unroll
    for (int q = 0; q < 8; q++) { rZ[q] = 0.f; rS[q] = 0.f; }
#pragma unroll
    for (int q = 0; q < 16; q++) { cZ[q] = 0.f; cS[q] = 0.f; }

#pragma unroll
    for (int mt = 0; mt < 4; mt++)
#pragma unroll
        for (int nt = 0; nt < 8; nt++)
#pragma unroll
            for (int hb = 0; hb < 2; hb++) {
                float2 pv = __half22float2(*(__half2*)&acc[mt][nt][hb]);
                int gi = r_base + mt * 16 + hb * 8;
                int li = labR[mt * 2 + hb];
#pragma unroll
                for (int d = 0; d < 2; d++) {
                    float sv = lsc * (d ? pv.y : pv.x);
                    float ex = fexp(sv);
                    int gj = c_base + nt * 8 + d;
                    bool tg = (gi == gj) || (li >= 0 && li == labC[nt * 2 + d]);
                    float ms = tg ? sv : 0.f;
                    rZ[mt * 2 + hb] += ex; rS[mt * 2 + hb] += ms;
                    cZ[nt * 2 + d] += ex;  cS[nt * 2 + d] += ms;
                }
            }

    // rows: reduce across the 4 lanes of each quad
#pragma unroll
    for (int m = 1; m <= 2; m <<= 1)
#pragma unroll
        for (int q = 0; q < 8; q++) {
            rZ[q] += __shfl_xor_sync(0xffffffffu, rZ[q], m);
            rS[q] += __shfl_xor_sync(0xffffffffu, rS[q], m);
        }
    if ((lane & 3) == 0) {
#pragma unroll
        for (int q = 0; q < 8; q++) {
            int gi = r_base + (q >> 1) * 16 + (q & 1) * 8;
            atomicAdd(&g_rowZ[gi], rZ[q]);
            atomicAdd(&g_rowS[gi], rS[q]);
        }
    }

    // cols: reduce across lane>>2
#pragma unroll
    for (int m = 4; m <= 16; m <<= 1)
#pragma unroll
        for (int q = 0; q < 16; q++) {
            cZ[q] += __shfl_xor_sync(0xffffffffu, cZ[q], m);
            cS[q] += __shfl_xor_sync(0xffffffffu, cS[q], m);
        }
    if (lane < 4) {
#pragma unroll
        for (int q = 0; q < 16; q++) {
            int gj = j0 + wn * 64 + (q >> 1) * 8 + 2 * lane + (q & 1);
            atomicAdd(&g_colZ[gj], cZ[q]);
            atomicAdd(&g_colS[gj], cS[q]);
        }
    }

    // ---- distributed final reduction ----
    __threadfence();          // make this CTA's stat atomics visible
    __syncthreads();
    __shared__ int fR, fC, fLast;
    if (tid == 0) {
        fR = (atomicAdd(&g_rc[blockIdx.y], 1) == 31);   // last of 32 j-tiles
        fC = (atomicAdd(&g_cc[blockIdx.x], 1) == 63);   // last of 64 i-tiles
    }
    __syncthreads();

    if (fR) {                 // rows i0..i0+127 complete: reduce row losses
        __threadfence();
        float part = 0.f;
        if (tid < 128) {
            int i = i0 + tid;
            int l = g_lab[i];
            float inv = (l < 0) ? 1.f : 1.f / (float)g_hist[l & 1023];
            part = logf(__ldcg(&g_rowZ[i])) - __ldcg(&g_rowS[i]) * inv;
        }
#pragma unroll
        for (int m = 16; m; m >>= 1) part += __shfl_xor_sync(0xffffffffu, part, m);
        if (lane == 0 && wid < 4) atomicAdd(&g_loss, part);
    }
    if (fC) {                 // cols j0..j0+255 complete: reduce col losses
        __threadfence();
        int j = j0 + tid;
        int l = g_lab[j];
        float inv = (l < 0) ? 1.f : 1.f / (float)g_hist[l & 1023];
        float part = logf(__ldcg(&g_colZ[j])) - __ldcg(&g_colS[j]) * inv;
#pragma unroll
        for (int m = 16; m; m >>= 1) part += __shfl_xor_sync(0xffffffffu, part, m);
        if (lane == 0) atomicAdd(&g_loss, part);
    }

    // ---- global completion: last CTA emits the result + resets replay state ----
    __threadfence();          // loss contributions visible before arrival
    __syncthreads();          // all threads of this CTA past their adds
    if (tid == 0) fLast = (atomicAdd(&g_done, 1) == 2047);
    __syncthreads();
    if (fLast) {
        __threadfence();
        if (tid == 0) {
            out[0] = __ldcg(&g_loss) / (2.0f * NROWS);
            g_loss = 0.f;
            g_done = 0;
        }
        if (tid < 64) g_rc[tid] = 0;
        if (tid < 32) g_cc[tid] = 0;
        for (int i = tid; i < 1024; i += 256) g_hist[i] = 0;
    }
}

// ---------------- launch ----------------
extern "C" void kernel_launch(void* const* d_in, const int* in_sizes, int n_in,
                              void* d_out, int out_size) {
    const float* txt = (const float*)d_in[0];
    const float* img = (const float*)d_in[1];
    const int*   lab = (const int*)d_in[2];

    cudaFuncSetAttribute(k_gemm, cudaFuncAttributeMaxDynamicSharedMemorySize,
                         2 * STAGE_BYTES);

    k_norm<<<2048, 256>>>(img, txt, lab);             // launch 0 (norm + init)
    dim3 grid(32, 64);
    k_gemm<<<grid, 256, 2 * STAGE_BYTES>>>((float*)d_out);  // launch 1 (everything else)
}